// round 1
// baseline (speedup 1.0000x reference)
#include <cuda_runtime.h>
#include <cstdint>

#define IN_F   256
#define OUT_F  128
#define MAX_NODES 100000

// Scratch for sup = x @ W  (100000 x 128 fp32 = 51.2 MB)
__device__ float g_sup[(size_t)MAX_NODES * OUT_F];

// ---------------------------------------------------------------------------
// GEMM: sup[n, 128] = x[n, 256] @ W[256, 128]
// Block = 256 threads (8 warps), tile = 32 rows x 128 cols.
// Each warp: 4 rows; each lane: 4 consecutive cols (float4 of W).
// x tile staged in smem (32 KB), broadcast reads; W read as float4 (L1/L2 resident).
// ---------------------------------------------------------------------------
__global__ __launch_bounds__(256) void gemm_kernel(
    const float* __restrict__ x, const float* __restrict__ W, int n_rows)
{
    __shared__ float xs[32 * IN_F];   // 32 KB

    int row0 = blockIdx.x * 32;
    int rows_here = n_rows - row0;
    if (rows_here > 32) rows_here = 32;

    // Stage x tile (coalesced float4)
    const float4* xg  = (const float4*)(x + (size_t)row0 * IN_F);
    float4*       xsv = (float4*)xs;
    int tile_f4 = rows_here * (IN_F / 4);
    for (int i = threadIdx.x; i < tile_f4; i += blockDim.x)
        xsv[i] = xg[i];
    __syncthreads();

    int warp = threadIdx.x >> 5;
    int lane = threadIdx.x & 31;
    int r0   = warp * 4;              // row within tile

    float4 acc0 = make_float4(0.f, 0.f, 0.f, 0.f);
    float4 acc1 = acc0, acc2 = acc0, acc3 = acc0;

    const float4* Wv = (const float4*)W;      // [256][32] float4
    const float*  x0 = xs + r0 * IN_F;

    #pragma unroll 8
    for (int k = 0; k < IN_F; k++) {
        float4 w = Wv[k * (OUT_F / 4) + lane];
        float a0 = x0[k];
        float a1 = x0[IN_F + k];
        float a2 = x0[2 * IN_F + k];
        float a3 = x0[3 * IN_F + k];
        acc0.x += a0 * w.x; acc0.y += a0 * w.y; acc0.z += a0 * w.z; acc0.w += a0 * w.w;
        acc1.x += a1 * w.x; acc1.y += a1 * w.y; acc1.z += a1 * w.z; acc1.w += a1 * w.w;
        acc2.x += a2 * w.x; acc2.y += a2 * w.y; acc2.z += a2 * w.z; acc2.w += a2 * w.w;
        acc3.x += a3 * w.x; acc3.y += a3 * w.y; acc3.z += a3 * w.z; acc3.w += a3 * w.w;
    }

    int gr = row0 + r0;
    if (gr + 0 < n_rows) ((float4*)(g_sup + (size_t)(gr + 0) * OUT_F))[lane] = acc0;
    if (gr + 1 < n_rows) ((float4*)(g_sup + (size_t)(gr + 1) * OUT_F))[lane] = acc1;
    if (gr + 2 < n_rows) ((float4*)(g_sup + (size_t)(gr + 2) * OUT_F))[lane] = acc2;
    if (gr + 3 < n_rows) ((float4*)(g_sup + (size_t)(gr + 3) * OUT_F))[lane] = acc3;
}

// ---------------------------------------------------------------------------
// Init: out[r, c] = b[c]   (bias broadcast; also clears the 0xAA poison)
// ---------------------------------------------------------------------------
__global__ void init_kernel(float* __restrict__ out, const float* __restrict__ b,
                            int n_rows)
{
    size_t i = (size_t)blockIdx.x * blockDim.x + threadIdx.x;
    size_t total = (size_t)n_rows * (OUT_F / 4);
    if (i < total) {
        float4 bv = ((const float4*)b)[i & (OUT_F / 4 - 1)];
        ((float4*)out)[i] = bv;
    }
}

// ---------------------------------------------------------------------------
// SpMM scatter: for each edge e: out[row[e]] += val[e] * sup[col[e]]
// One warp per edge. Lane l handles features [4l, 4l+4): float4 gather of the
// 512B sup row, then vector reduction red.global.add.v4.f32 (sm_90+).
// ---------------------------------------------------------------------------
__global__ __launch_bounds__(256) void spmm_kernel(
    const int* __restrict__ erow, const int* __restrict__ ecol,
    const float* __restrict__ eval, float* __restrict__ out, int n_edges)
{
    int gw   = (int)(((size_t)blockIdx.x * blockDim.x + threadIdx.x) >> 5);
    int lane = threadIdx.x & 31;
    if (gw >= n_edges) return;

    int   r = __ldg(erow + gw);
    int   c = __ldg(ecol + gw);
    float v = __ldg(eval + gw);

    float4 s = __ldg((const float4*)(g_sup + (size_t)c * OUT_F) + lane);
    float4 m = make_float4(v * s.x, v * s.y, v * s.z, v * s.w);

    float* dst = out + (size_t)r * OUT_F + lane * 4;
    asm volatile("red.global.add.v4.f32 [%0], {%1, %2, %3, %4};"
                 :: "l"(dst), "f"(m.x), "f"(m.y), "f"(m.z), "f"(m.w)
                 : "memory");
}

// ---------------------------------------------------------------------------
extern "C" void kernel_launch(void* const* d_in, const int* in_sizes, int n_in,
                              void* d_out, int out_size)
{
    const float* x    = (const float*)d_in[0];
    const int*   erow = (const int*)  d_in[1];
    const int*   ecol = (const int*)  d_in[2];
    const float* eval = (const float*)d_in[3];
    const float* W    = (const float*)d_in[4];
    const float* b    = (const float*)d_in[5];
    float*       out  = (float*)d_out;

    int n_rows  = in_sizes[0] / IN_F;
    int n_edges = in_sizes[3];

    // 1) sup = x @ W
    int gemm_blocks = (n_rows + 31) / 32;
    gemm_kernel<<<gemm_blocks, 256>>>(x, W, n_rows);

    // 2) out = b (broadcast)
    size_t total4 = (size_t)n_rows * (OUT_F / 4);
    int init_blocks = (int)((total4 + 255) / 256);
    init_kernel<<<init_blocks, 256>>>(out, b, n_rows);

    // 3) scatter-add edges
    int spmm_blocks = (n_edges + 7) / 8;   // 8 warps per 256-thread block
    spmm_kernel<<<spmm_blocks, 256>>>(erow, ecol, eval, out, n_edges);
}

// round 2
// speedup vs baseline: 1.1849x; 1.1849x over previous
#include <cuda_runtime.h>
#include <cstdint>

#define IN_F   256
#define OUT_F  128
#define MAX_NODES 100000
#define MAX_EDGES 1600000

// Scratch (static __device__ globals: allocation-guard-safe)
__device__ float g_sup[(size_t)MAX_NODES * OUT_F];          // 51.2 MB
__device__ uint2 g_epack[MAX_EDGES];                        // 12.8 MB (col, val-bits)
__device__ int   g_counts[MAX_NODES];
__device__ int   g_offs[MAX_NODES + 1];
__device__ int   g_cursor[MAX_NODES];

// ---------------------------------------------------------------------------
// GEMM: sup[n, 128] = x[n, 256] @ W[256, 128]   (unchanged from R1; ~203us,
// near scalar-FFMA floor. Tensor-core version is the next round's change.)
// ---------------------------------------------------------------------------
__global__ __launch_bounds__(256) void gemm_kernel(
    const float* __restrict__ x, const float* __restrict__ W, int n_rows)
{
    __shared__ float xs[32 * IN_F];   // 32 KB

    int row0 = blockIdx.x * 32;
    int rows_here = n_rows - row0;
    if (rows_here > 32) rows_here = 32;

    const float4* xg  = (const float4*)(x + (size_t)row0 * IN_F);
    float4*       xsv = (float4*)xs;
    int tile_f4 = rows_here * (IN_F / 4);
    for (int i = threadIdx.x; i < tile_f4; i += blockDim.x)
        xsv[i] = xg[i];
    __syncthreads();

    int warp = threadIdx.x >> 5;
    int lane = threadIdx.x & 31;
    int r0   = warp * 4;

    float4 acc0 = make_float4(0.f, 0.f, 0.f, 0.f);
    float4 acc1 = acc0, acc2 = acc0, acc3 = acc0;

    const float4* Wv = (const float4*)W;
    const float*  x0 = xs + r0 * IN_F;

    #pragma unroll 8
    for (int k = 0; k < IN_F; k++) {
        float4 w = Wv[k * (OUT_F / 4) + lane];
        float a0 = x0[k];
        float a1 = x0[IN_F + k];
        float a2 = x0[2 * IN_F + k];
        float a3 = x0[3 * IN_F + k];
        acc0.x += a0 * w.x; acc0.y += a0 * w.y; acc0.z += a0 * w.z; acc0.w += a0 * w.w;
        acc1.x += a1 * w.x; acc1.y += a1 * w.y; acc1.z += a1 * w.z; acc1.w += a1 * w.w;
        acc2.x += a2 * w.x; acc2.y += a2 * w.y; acc2.z += a2 * w.z; acc2.w += a2 * w.w;
        acc3.x += a3 * w.x; acc3.y += a3 * w.y; acc3.z += a3 * w.z; acc3.w += a3 * w.w;
    }

    int gr = row0 + r0;
    if (gr + 0 < n_rows) ((float4*)(g_sup + (size_t)(gr + 0) * OUT_F))[lane] = acc0;
    if (gr + 1 < n_rows) ((float4*)(g_sup + (size_t)(gr + 1) * OUT_F))[lane] = acc1;
    if (gr + 2 < n_rows) ((float4*)(g_sup + (size_t)(gr + 2) * OUT_F))[lane] = acc2;
    if (gr + 3 < n_rows) ((float4*)(g_sup + (size_t)(gr + 3) * OUT_F))[lane] = acc3;
}

// ---------------------------------------------------------------------------
// CSR build
// ---------------------------------------------------------------------------
__global__ void zero_kernel(int n)
{
    int i = blockIdx.x * blockDim.x + threadIdx.x;
    if (i < n) { g_counts[i] = 0; g_cursor[i] = 0; }
}

__global__ void hist_kernel(const int* __restrict__ erow, int n_edges)
{
    int e = blockIdx.x * blockDim.x + threadIdx.x;
    if (e < n_edges) atomicAdd(&g_counts[erow[e]], 1);
}

// Single-block exclusive scan: offs[0]=0, offs[i+1] = sum counts[0..i]
__global__ __launch_bounds__(1024) void scan_kernel(int n)
{
    __shared__ int wsums[32];
    __shared__ int carry_sh;
    int tid = threadIdx.x, lane = tid & 31, wid = tid >> 5;
    if (tid == 0) { carry_sh = 0; g_offs[0] = 0; }
    __syncthreads();

    for (int base = 0; base < n; base += 1024) {
        int i = base + tid;
        int v = (i < n) ? g_counts[i] : 0;
        int incl = v;
        #pragma unroll
        for (int o = 1; o < 32; o <<= 1) {
            int t = __shfl_up_sync(0xffffffffu, incl, o);
            if (lane >= o) incl += t;
        }
        if (lane == 31) wsums[wid] = incl;
        __syncthreads();
        if (wid == 0) {
            int ws = wsums[lane];
            int wincl = ws;
            #pragma unroll
            for (int o = 1; o < 32; o <<= 1) {
                int t = __shfl_up_sync(0xffffffffu, wincl, o);
                if (lane >= o) wincl += t;
            }
            wsums[lane] = wincl - ws;          // exclusive warp prefix
        }
        __syncthreads();
        int val = incl + wsums[wid] + carry_sh; // inclusive global prefix
        if (i < n) g_offs[i + 1] = val;
        __syncthreads();
        if (tid == 1023) carry_sh = val;        // padding v=0 keeps this exact
        __syncthreads();
    }
}

__global__ void scatter_kernel(const int* __restrict__ erow,
                               const int* __restrict__ ecol,
                               const float* __restrict__ eval, int n_edges)
{
    int e = blockIdx.x * blockDim.x + threadIdx.x;
    if (e >= n_edges) return;
    int r = erow[e];
    int pos = atomicAdd(&g_cursor[r], 1);
    g_epack[g_offs[r] + pos] = make_uint2((unsigned)ecol[e], __float_as_uint(eval[e]));
}

// ---------------------------------------------------------------------------
// Gather SpMM: one warp per destination row. Lane l owns features [4l,4l+4).
// out[r] = b + sum_{e in row r} val[e] * sup[col[e]]      (no atomics, no init)
// ---------------------------------------------------------------------------
__global__ __launch_bounds__(256) void spmm_csr_kernel(
    const float* __restrict__ b, float* __restrict__ out, int n_rows)
{
    int row  = (int)(((size_t)blockIdx.x * blockDim.x + threadIdx.x) >> 5);
    int lane = threadIdx.x & 31;
    if (row >= n_rows) return;

    int s = g_offs[row], e = g_offs[row + 1];

    float4 acc = __ldg((const float4*)b + lane);   // bias

    for (int base = s; base < e; base += 32) {
        int n = e - base; if (n > 32) n = 32;
        uint2 ed = make_uint2(0u, 0u);
        if (lane < n) ed = g_epack[base + lane];
        for (int j = 0; j < n; j++) {
            int   c = (int)__shfl_sync(0xffffffffu, ed.x, j);
            float v = __uint_as_float(__shfl_sync(0xffffffffu, ed.y, j));
            float4 sv = __ldg((const float4*)(g_sup + (size_t)c * OUT_F) + lane);
            acc.x += v * sv.x; acc.y += v * sv.y;
            acc.z += v * sv.z; acc.w += v * sv.w;
        }
    }

    ((float4*)(out + (size_t)row * OUT_F))[lane] = acc;
}

// ---------------------------------------------------------------------------
extern "C" void kernel_launch(void* const* d_in, const int* in_sizes, int n_in,
                              void* d_out, int out_size)
{
    const float* x    = (const float*)d_in[0];
    const int*   erow = (const int*)  d_in[1];
    const int*   ecol = (const int*)  d_in[2];
    const float* eval = (const float*)d_in[3];
    const float* W    = (const float*)d_in[4];
    const float* b    = (const float*)d_in[5];
    float*       out  = (float*)d_out;

    int n_rows  = in_sizes[0] / IN_F;
    int n_edges = in_sizes[3];

    // 1) sup = x @ W
    gemm_kernel<<<(n_rows + 31) / 32, 256>>>(x, W, n_rows);

    // 2) CSR build
    zero_kernel<<<(n_rows + 255) / 256, 256>>>(n_rows);
    hist_kernel<<<(n_edges + 255) / 256, 256>>>(erow, n_edges);
    scan_kernel<<<1, 1024>>>(n_rows);
    scatter_kernel<<<(n_edges + 255) / 256, 256>>>(erow, ecol, eval, n_edges);

    // 3) gather spmm + bias
    int warps = n_rows;
    int blocks = (int)(((size_t)warps * 32 + 255) / 256);
    spmm_csr_kernel<<<blocks, 256>>>(b, out, n_rows);
}

// round 4
// speedup vs baseline: 1.2936x; 1.0917x over previous
#include <cuda_runtime.h>
#include <cuda_bf16.h>
#include <cstdint>

#define IN_F   256
#define OUT_F  128
#define MAX_NODES 100000
#define MAX_EDGES 1600000

// ---- scratch (__device__ globals: allocation-guard-safe) -------------------
__device__ float    g_sup[(size_t)MAX_NODES * OUT_F];     // 51.2 MB
__device__ uint2    g_epack[MAX_EDGES];                   // 12.8 MB (col, val)
__device__ int      g_counts[MAX_NODES];
__device__ int      g_offs[MAX_NODES + 1];
__device__ int      g_cursor[MAX_NODES];
__device__ int      g_bsums[1024];
__device__ int      g_bpre[1024];
// W in bf16 hi/lo, transposed to [col][k] so B-fragment k-pairs are one u32
__device__ __nv_bfloat16 g_Wt_hi[OUT_F * IN_F];
__device__ __nv_bfloat16 g_Wt_lo[OUT_F * IN_F];

// ===========================================================================
// W convert: Wt_hi[c][k] = bf16(W[k][c]),  Wt_lo = bf16(residual)
// ===========================================================================
__global__ void wconv_kernel(const float* __restrict__ W)
{
    int i = blockIdx.x * blockDim.x + threadIdx.x;   // i = k*OUT_F + c
    if (i >= IN_F * OUT_F) return;
    int k = i / OUT_F, c = i % OUT_F;
    float w = W[i];
    __nv_bfloat16 h = __float2bfloat16(w);
    __nv_bfloat16 l = __float2bfloat16(w - __bfloat162float(h));
    g_Wt_hi[c * IN_F + k] = h;
    g_Wt_lo[c * IN_F + k] = l;
}

// ===========================================================================
// Tensor-core GEMM: sup = x @ W via mma.sync m16n8k16 bf16, split-bf16 x3:
//   x = xh + xl, W = wh + wl;  sup ≈ xh*wh + xh*wl + xl*wh  (fp32 accum)
// Block = 256 thr (8 warps), tile 32 rows x 128 cols. warp tile: m16 x n32.
// Static smem: 2 * 32 * 132 * 4 B = 33.8 KB (< 48 KB, no attribute needed).
// ===========================================================================
#define XS_STRIDE 132   // u32 per row: 128 data + 4 pad

__device__ __forceinline__ void mma_bf16(
    float& c0, float& c1, float& c2, float& c3,
    uint32_t a0, uint32_t a1, uint32_t a2, uint32_t a3,
    uint32_t b0, uint32_t b1)
{
    asm volatile(
        "mma.sync.aligned.m16n8k16.row.col.f32.bf16.bf16.f32 "
        "{%0,%1,%2,%3}, {%4,%5,%6,%7}, {%8,%9}, {%0,%1,%2,%3};"
        : "+f"(c0), "+f"(c1), "+f"(c2), "+f"(c3)
        : "r"(a0), "r"(a1), "r"(a2), "r"(a3), "r"(b0), "r"(b1));
}

__global__ __launch_bounds__(256) void gemm_mma_kernel(
    const float* __restrict__ x, int n_rows)
{
    __shared__ uint32_t xs_hi[32 * XS_STRIDE];
    __shared__ uint32_t xs_lo[32 * XS_STRIDE];

    int row0 = blockIdx.x * 32;

    // Stage x tile: fp32 -> bf16 hi/lo packed k-pairs in smem
    for (int i = threadIdx.x; i < 32 * 128; i += 256) {
        int r  = i >> 7;            // 0..31
        int kp = i & 127;           // u32 (k-pair) index
        int gr = row0 + r;
        float2 v = make_float2(0.f, 0.f);
        if (gr < n_rows) v = *(const float2*)(x + (size_t)gr * IN_F + kp * 2);
        __nv_bfloat16 h0 = __float2bfloat16(v.x);
        __nv_bfloat16 h1 = __float2bfloat16(v.y);
        __nv_bfloat16 l0 = __float2bfloat16(v.x - __bfloat162float(h0));
        __nv_bfloat16 l1 = __float2bfloat16(v.y - __bfloat162float(h1));
        xs_hi[r * XS_STRIDE + kp] =
            ((uint32_t)__bfloat16_as_ushort(h1) << 16) | __bfloat16_as_ushort(h0);
        xs_lo[r * XS_STRIDE + kp] =
            ((uint32_t)__bfloat16_as_ushort(l1) << 16) | __bfloat16_as_ushort(l0);
    }
    __syncthreads();

    int warp = threadIdx.x >> 5;
    int lane = threadIdx.x & 31;
    int wm = warp & 1;              // m sub-tile (16 rows)
    int wn = warp >> 1;             // n slice (32 cols)
    int qr = lane >> 2;             // 0..7
    int qc = lane & 3;              // 0..3

    float acc[4][4];
    #pragma unroll
    for (int nb = 0; nb < 4; nb++)
        acc[nb][0] = acc[nb][1] = acc[nb][2] = acc[nb][3] = 0.f;

    const uint32_t* Ah = xs_hi + (wm * 16 + qr) * XS_STRIDE + qc;
    const uint32_t* Al = xs_lo + (wm * 16 + qr) * XS_STRIDE + qc;
    const uint32_t* Bh = (const uint32_t*)g_Wt_hi;   // [128 cols][128 u32]
    const uint32_t* Bl = (const uint32_t*)g_Wt_lo;

    #pragma unroll 4
    for (int s = 0; s < 16; s++) {
        int k0 = s * 8;             // u32 offset of this k16 step
        uint32_t a0h = Ah[k0],     a1h = Ah[8 * XS_STRIDE + k0];
        uint32_t a2h = Ah[k0 + 4], a3h = Ah[8 * XS_STRIDE + k0 + 4];
        uint32_t a0l = Al[k0],     a1l = Al[8 * XS_STRIDE + k0];
        uint32_t a2l = Al[k0 + 4], a3l = Al[8 * XS_STRIDE + k0 + 4];

        #pragma unroll
        for (int nb = 0; nb < 4; nb++) {
            int col = wn * 32 + nb * 8 + qr;
            uint32_t b0h = __ldg(Bh + col * 128 + k0 + qc);
            uint32_t b1h = __ldg(Bh + col * 128 + k0 + qc + 4);
            uint32_t b0l = __ldg(Bl + col * 128 + k0 + qc);
            uint32_t b1l = __ldg(Bl + col * 128 + k0 + qc + 4);
            mma_bf16(acc[nb][0], acc[nb][1], acc[nb][2], acc[nb][3],
                     a0h, a1h, a2h, a3h, b0h, b1h);
            mma_bf16(acc[nb][0], acc[nb][1], acc[nb][2], acc[nb][3],
                     a0h, a1h, a2h, a3h, b0l, b1l);
            mma_bf16(acc[nb][0], acc[nb][1], acc[nb][2], acc[nb][3],
                     a0l, a1l, a2l, a3l, b0h, b1h);
        }
    }

    // Store C fragments
    int r_lo = row0 + wm * 16 + qr;
    int r_hi = r_lo + 8;
    #pragma unroll
    for (int nb = 0; nb < 4; nb++) {
        int col = wn * 32 + nb * 8 + qc * 2;
        if (r_lo < n_rows)
            *(float2*)(g_sup + (size_t)r_lo * OUT_F + col) = make_float2(acc[nb][0], acc[nb][1]);
        if (r_hi < n_rows)
            *(float2*)(g_sup + (size_t)r_hi * OUT_F + col) = make_float2(acc[nb][2], acc[nb][3]);
    }
}

// ===========================================================================
// CSR build
// ===========================================================================
__global__ void zero_kernel(int n)
{
    int i = blockIdx.x * blockDim.x + threadIdx.x;
    if (i < n) { g_counts[i] = 0; g_cursor[i] = 0; }
}

__global__ void hist_kernel(const int* __restrict__ erow, int n_edges)
{
    int e = blockIdx.x * blockDim.x + threadIdx.x;
    if (e < n_edges) atomicAdd(&g_counts[erow[e]], 1);
}

// pass 1: per-block inclusive scan of 1024 counts
__global__ __launch_bounds__(1024) void scan1_kernel(int n)
{
    __shared__ int wsums[32];
    int tid = threadIdx.x, lane = tid & 31, wid = tid >> 5;
    int i = blockIdx.x * 1024 + tid;
    int v = (i < n) ? g_counts[i] : 0;
    int incl = v;
    #pragma unroll
    for (int o = 1; o < 32; o <<= 1) {
        int t = __shfl_up_sync(0xffffffffu, incl, o);
        if (lane >= o) incl += t;
    }
    if (lane == 31) wsums[wid] = incl;
    __syncthreads();
    if (wid == 0) {
        int ws = wsums[lane];
        int wi = ws;
        #pragma unroll
        for (int o = 1; o < 32; o <<= 1) {
            int t = __shfl_up_sync(0xffffffffu, wi, o);
            if (lane >= o) wi += t;
        }
        wsums[lane] = wi - ws;
    }
    __syncthreads();
    int val = incl + wsums[wid];
    if (i < n) g_offs[i + 1] = val;             // local inclusive
    if (tid == 1023) g_bsums[blockIdx.x] = val; // block total
    if (i == 0) g_offs[0] = 0;
}

// pass 2: single-block exclusive scan of block sums (nblk <= 1024)
__global__ __launch_bounds__(1024) void scan2_kernel(int nblk)
{
    __shared__ int wsums[32];
    int tid = threadIdx.x, lane = tid & 31, wid = tid >> 5;
    int v = (tid < nblk) ? g_bsums[tid] : 0;
    int incl = v;
    #pragma unroll
    for (int o = 1; o < 32; o <<= 1) {
        int t = __shfl_up_sync(0xffffffffu, incl, o);
        if (lane >= o) incl += t;
    }
    if (lane == 31) wsums[wid] = incl;
    __syncthreads();
    if (wid == 0) {
        int ws = wsums[lane];
        int wi = ws;
        #pragma unroll
        for (int o = 1; o < 32; o <<= 1) {
            int t = __shfl_up_sync(0xffffffffu, wi, o);
            if (lane >= o) wi += t;
        }
        wsums[lane] = wi - ws;
    }
    __syncthreads();
    if (tid < nblk) g_bpre[tid] = incl + wsums[wid] - v;   // exclusive
}

// pass 3: add block prefixes
__global__ void scan3_kernel(int n)
{
    int i = blockIdx.x * blockDim.x + threadIdx.x;
    if (i < n) g_offs[i + 1] += g_bpre[i >> 10];
}

__global__ void scatter_kernel(const int* __restrict__ erow,
                               const int* __restrict__ ecol,
                               const float* __restrict__ eval, int n_edges)
{
    int e = blockIdx.x * blockDim.x + threadIdx.x;
    if (e >= n_edges) return;
    int r = erow[e];
    int pos = atomicAdd(&g_cursor[r], 1);
    g_epack[g_offs[r] + pos] = make_uint2((unsigned)ecol[e], __float_as_uint(eval[e]));
}

// ===========================================================================
// Gather SpMM: one warp per destination row; bias folded in; no atomics.
// ===========================================================================
__global__ __launch_bounds__(256) void spmm_csr_kernel(
    const float* __restrict__ b, float* __restrict__ out, int n_rows)
{
    int row  = (int)(((size_t)blockIdx.x * blockDim.x + threadIdx.x) >> 5);
    int lane = threadIdx.x & 31;
    if (row >= n_rows) return;

    int s = g_offs[row], e = g_offs[row + 1];
    float4 acc = __ldg((const float4*)b + lane);

    for (int base = s; base < e; base += 32) {
        int n = e - base; if (n > 32) n = 32;
        uint2 ed = make_uint2(0u, 0u);
        if (lane < n) ed = g_epack[base + lane];
        for (int j = 0; j < n; j++) {
            int   c = (int)__shfl_sync(0xffffffffu, ed.x, j);
            float v = __uint_as_float(__shfl_sync(0xffffffffu, ed.y, j));
            float4 sv = __ldg((const float4*)(g_sup + (size_t)c * OUT_F) + lane);
            acc.x += v * sv.x; acc.y += v * sv.y;
            acc.z += v * sv.z; acc.w += v * sv.w;
        }
    }
    ((float4*)(out + (size_t)row * OUT_F))[lane] = acc;
}

// ===========================================================================
extern "C" void kernel_launch(void* const* d_in, const int* in_sizes, int n_in,
                              void* d_out, int out_size)
{
    const float* x    = (const float*)d_in[0];
    const int*   erow = (const int*)  d_in[1];
    const int*   ecol = (const int*)  d_in[2];
    const float* eval = (const float*)d_in[3];
    const float* W    = (const float*)d_in[4];
    const float* b    = (const float*)d_in[5];
    float*       out  = (float*)d_out;

    int n_rows  = in_sizes[0] / IN_F;
    int n_edges = in_sizes[3];

    // GEMM (tensor cores, split-bf16 x3)
    wconv_kernel<<<(IN_F * OUT_F + 255) / 256, 256>>>(W);
    gemm_mma_kernel<<<(n_rows + 31) / 32, 256>>>(x, n_rows);

    // CSR build
    zero_kernel<<<(n_rows + 255) / 256, 256>>>(n_rows);
    hist_kernel<<<(n_edges + 255) / 256, 256>>>(erow, n_edges);
    int nblk = (n_rows + 1023) / 1024;
    scan1_kernel<<<nblk, 1024>>>(n_rows);
    scan2_kernel<<<1, 1024>>>(nblk);
    scan3_kernel<<<(n_rows + 255) / 256, 256>>>(n_rows);
    scatter_kernel<<<(n_edges + 255) / 256, 256>>>(erow, ecol, eval, n_edges);

    // gather spmm + bias
    int blocks = (int)(((size_t)n_rows * 32 + 255) / 256);
    spmm_csr_kernel<<<blocks, 256>>>(b, out, n_rows);
}